// round 16
// baseline (speedup 1.0000x reference)
#include <cuda_runtime.h>
#include <cuda_bf16.h>
#include <math.h>
#include <stdint.h>

#define B_ 256
#define T_ 128
#define D_ 256
#define H_ 512
#define BT_ (B_*T_)
#define G4H_ 2048
#define XHAT_OFF (T_*B_*2)   /* outs [T,B,2] first, then xhats [T,B,D] */
#define LDK 132              /* loop smem row: Kc=128 + 4 pad */
#define NCTA_GROUP 64        /* loop: 4 independent groups of 64 CTAs */
#define LDF 72               /* bf16 frag-tile row stride: 144B, 16B-aligned, cf */

// ---- device scratch (allocation-free rule) ----
__device__ float g_gammaH[(size_t)T_*B_*H_];      // [T,B,H]
__device__ float g_preGates[(size_t)T_*B_*G4H_];  // [T,B,4H]
__device__ float g_part[4][B_][G4H_];             // split-K partials
__device__ float g_hbuf[2][B_][H_];               // double-buffered h (for head)
__device__ float g_ah[2][B_][H_];                 // double-buffered gamma_h ⊙ h
__device__ float g_wT[(D_+H_)*D_];                // wgxT [256,256] then wghT [512,256]
__device__ float g_W1T[10*H_];                    // W1 transposed [10][512]
__device__ unsigned g_barC[4][32];                // per-group barrier counter
__device__ unsigned g_barS[4][32];                // per-group barrier flag

typedef unsigned long long u64;
union F2U { u64 u; float2 f; };

__device__ __forceinline__ u64 ffma2(u64 a, u64 b, u64 c) {
    u64 d; asm("fma.rn.f32x2 %0,%1,%2,%3;" : "=l"(d) : "l"(a), "l"(b), "l"(c)); return d;
}
__device__ __forceinline__ float sigm(float x){ return 1.f/(1.f+expf(-x)); }
__device__ __forceinline__ float ldcg(const float* p){
    float v; asm volatile("ld.global.cg.f32 %0,[%1];" : "=f"(v) : "l"(p)); return v;
}
__device__ __forceinline__ float4 ldcg4(const float* p){
    float4 v; asm volatile("ld.global.cg.v4.f32 {%0,%1,%2,%3},[%4];"
        : "=f"(v.x),"=f"(v.y),"=f"(v.z),"=f"(v.w) : "l"(p)); return v;
}
__device__ __forceinline__ void stcg(float* p, float v){
    asm volatile("st.global.cg.f32 [%0],%1;" :: "l"(p), "f"(v));
}
__device__ __forceinline__ uint32_t s2u(const void* p){
    uint32_t a;
    asm("{ .reg .u64 t; cvta.to.shared.u64 t, %1; cvt.u32.u64 %0, t; }" : "=r"(a) : "l"(p));
    return a;
}

// ============================================================================
// HMMA bf16x3 GEMM machinery (mma.sync m16n8k16) — pre-GEMMs only (R10 proven)
// ============================================================================
__device__ __forceinline__ void ldm4(uint32_t* r, uint32_t addr){
    asm volatile("ldmatrix.sync.aligned.m8n8.x4.shared.b16 {%0,%1,%2,%3}, [%4];"
        : "=r"(r[0]),"=r"(r[1]),"=r"(r[2]),"=r"(r[3]) : "r"(addr));
}
__device__ __forceinline__ void mma_bf16(float* d, const uint32_t* a,
                                         uint32_t b0, uint32_t b1){
    asm volatile("mma.sync.aligned.m16n8k16.row.col.f32.bf16.bf16.f32 "
        "{%0,%1,%2,%3}, {%4,%5,%6,%7}, {%8,%9}, {%0,%1,%2,%3};"
        : "+f"(d[0]), "+f"(d[1]), "+f"(d[2]), "+f"(d[3])
        : "r"(a[0]), "r"(a[1]), "r"(a[2]), "r"(a[3]), "r"(b0), "r"(b1));
}
__device__ __forceinline__ void split4(float4 v, uint2& hi, uint2& lo){
    __nv_bfloat162 h01 = __floats2bfloat162_rn(v.x, v.y);
    __nv_bfloat162 h23 = __floats2bfloat162_rn(v.z, v.w);
    __nv_bfloat162 l01 = __floats2bfloat162_rn(v.x - __bfloat162float(h01.x),
                                               v.y - __bfloat162float(h01.y));
    __nv_bfloat162 l23 = __floats2bfloat162_rn(v.z - __bfloat162float(h23.x),
                                               v.w - __bfloat162float(h23.y));
    hi = make_uint2(*(uint32_t*)&h01, *(uint32_t*)&h23);
    lo = make_uint2(*(uint32_t*)&l01, *(uint32_t*)&l23);
}

// Pre-GEMM core: acc[2][8][4] += A[128 @arow0][256] @ B[128 @brow0][256]^T
__device__ __forceinline__ void hmma_gemm(
    __nv_bfloat16* sm, const float* __restrict__ A, int arow0, int lda,
    const float* __restrict__ Bsrc, int brow0, int ldb, float acc[2][8][4])
{
    __nv_bfloat16 *sAhi = sm, *sAlo = sm + 128*LDF;
    __nv_bfloat16 *sBhi = sm + 2*128*LDF, *sBlo = sm + 3*128*LDF;
    const int tid = threadIdx.x, lane = tid & 31, wid = tid >> 5;
    const int wm = wid & 3, wn = wid >> 2;
    const int g = lane >> 3, r8 = lane & 7;

    for (int ch = 0; ch < 4; ch++) {
        const int k0 = ch*64;
        if (ch) __syncthreads();
        #pragma unroll 4
        for (int i = tid; i < 2048; i += 256) {
            int rr = i >> 4, q = (i & 15) << 2;
            uint2 hi, lo;
            split4(*(const float4*)&A[(size_t)(arow0+rr)*lda + k0 + q], hi, lo);
            *(uint2*)&sAhi[rr*LDF + q] = hi;
            *(uint2*)&sAlo[rr*LDF + q] = lo;
        }
        #pragma unroll 4
        for (int i = tid; i < 2048; i += 256) {
            int rr = i >> 4, q = (i & 15) << 2;
            uint2 hi, lo;
            split4(*(const float4*)&Bsrc[(size_t)(brow0+rr)*ldb + k0 + q], hi, lo);
            *(uint2*)&sBhi[rr*LDF + q] = hi;
            *(uint2*)&sBlo[rr*LDF + q] = lo;
        }
        __syncthreads();
        #pragma unroll
        for (int ks = 0; ks < 4; ks++) {
            const int kk = ks*16;
            uint32_t ahi[2][4], alo[2][4], bhi[4][4], blo[4][4];
            #pragma unroll
            for (int mi = 0; mi < 2; mi++) {
                int m = wm*32 + mi*16 + (g & 1)*8 + r8;
                int k = kk + (g >> 1)*8;
                ldm4(ahi[mi], s2u(&sAhi[m*LDF + k]));
                ldm4(alo[mi], s2u(&sAlo[m*LDF + k]));
            }
            #pragma unroll
            for (int np = 0; np < 4; np++) {
                int n = wn*64 + np*16 + (g >> 1)*8 + r8;
                int k = kk + (g & 1)*8;
                ldm4(bhi[np], s2u(&sBhi[n*LDF + k]));
                ldm4(blo[np], s2u(&sBlo[n*LDF + k]));
            }
            #pragma unroll
            for (int mi = 0; mi < 2; mi++)
                #pragma unroll
                for (int nj = 0; nj < 8; nj++) {
                    uint32_t h0 = bhi[nj>>1][(nj&1)*2], h1 = bhi[nj>>1][(nj&1)*2+1];
                    uint32_t l0 = blo[nj>>1][(nj&1)*2], l1 = blo[nj>>1][(nj&1)*2+1];
                    mma_bf16(acc[mi][nj], ahi[mi], h0, h1);
                    mma_bf16(acc[mi][nj], ahi[mi], l0, l1);
                    mma_bf16(acc[mi][nj], alo[mi], h0, h1);
                }
        }
    }
}
#define HM_SMEM (4*128*LDF*2)

// ---------------------------------------------------------------------------
// G12 (HMMA): gamma_x (+imputation->xhat) and gamma_h.  grid (BT/128, 6).
// ---------------------------------------------------------------------------
__global__ void __launch_bounds__(256,2) k_g12_h(
    const float* __restrict__ dt,  const float* __restrict__ hgx,
    const float* __restrict__ hgh, const float* __restrict__ x,
    const float* __restrict__ mask, const float* __restrict__ xmean,
    float* __restrict__ out)
{
    extern __shared__ __nv_bfloat16 smb[];
    float acc[2][8][4] = {};
    const int m0 = blockIdx.x*128, n0 = blockIdx.y*128;
    hmma_gemm(smb, dt, m0, D_, (const float*)g_wT, n0, D_, acc);

    const int lane = threadIdx.x & 31, wid = threadIdx.x >> 5;
    const int wm = wid & 3, wn = wid >> 2;
    const int tg = lane >> 2, tc = (lane & 3)*2;

    #pragma unroll
    for (int mi = 0; mi < 2; mi++) {
        #pragma unroll
        for (int nj = 0; nj < 8; nj++) {
            const float* a4 = acc[mi][nj];
            int ng = n0 + wn*64 + nj*8 + tc;
            #pragma unroll
            for (int h = 0; h < 2; h++) {
                int row = m0 + wm*32 + mi*16 + tg + h*8;   // = b*T + t
                int b = row >> 7, t = row & (T_-1);
                float v0 = a4[h*2], v1 = a4[h*2+1];
                if (blockIdx.y < 2) {
                    int d = ng;
                    float o[2];
                    #pragma unroll
                    for (int e = 0; e < 2; e++) {
                        float v = e ? v1 : v0; int dd = d + e;
                        float gm = expf(-fmaxf(v + hgx[dd], 0.f));
                        float mv = mask[(size_t)row*D_ + dd];
                        float xt = x[(size_t)row*D_ + dd];
                        float xm = xmean[dd];
                        float imp = (t == 0) ? xm
                                  : fmaf(gm, x[(size_t)(row-1)*D_ + dd], (1.f-gm)*xm);
                        o[e] = xt*mv + (1.f-mv)*imp;
                    }
                    *(float2*)&out[XHAT_OFF + ((size_t)t*B_ + b)*D_ + d] = make_float2(o[0], o[1]);
                } else {
                    int u = ng - 256;
                    float2 o;
                    o.x = expf(-fmaxf(v0 + hgh[u],   0.f));
                    o.y = expf(-fmaxf(v1 + hgh[u+1], 0.f));
                    *(float2*)&g_gammaH[((size_t)t*B_ + b)*H_ + u] = o;
                }
            }
        }
    }
}

// ---------------------------------------------------------------------------
// G3 (HMMA): pre_gates = xs @ W_ih^T + b_ih + b_hh.  grid (BT/128, 16).
// ---------------------------------------------------------------------------
__global__ void __launch_bounds__(256,2) k_g3_h(
    const float* __restrict__ xsrc, const float* __restrict__ Wih,
    const float* __restrict__ bih,  const float* __restrict__ bhh)
{
    extern __shared__ __nv_bfloat16 smb[];
    float acc[2][8][4] = {};
    const int m0 = blockIdx.x*128, n0 = blockIdx.y*128;
    hmma_gemm(smb, xsrc, m0, D_, Wih, n0, D_, acc);

    const int lane = threadIdx.x & 31, wid = threadIdx.x >> 5;
    const int wm = wid & 3, wn = wid >> 2;
    const int tg = lane >> 2, tc = (lane & 3)*2;

    #pragma unroll
    for (int mi = 0; mi < 2; mi++) {
        #pragma unroll
        for (int nj = 0; nj < 8; nj++) {
            const float* a4 = acc[mi][nj];
            int n = n0 + wn*64 + nj*8 + tc;
            float bi0 = bih[n] + bhh[n], bi1 = bih[n+1] + bhh[n+1];
            #pragma unroll
            for (int h = 0; h < 2; h++) {
                int row = m0 + wm*32 + mi*16 + tg + h*8;   // = t*B + b
                *(float2*)&g_preGates[(size_t)row*G4H_ + n] =
                    make_float2(a4[h*2] + bi0, a4[h*2+1] + bi1);
            }
        }
    }
}

// ============================================================================
// misc small kernels
// ============================================================================
// init h AND ah(0) = gammaH[0] ⊙ h0  (must run AFTER k_g12_h)
__global__ void __launch_bounds__(H_) k_init(const float* __restrict__ h0)
{
    int b = blockIdx.x, u = threadIdx.x;
    float h = h0[u];
    g_hbuf[0][b][u] = h;
    g_ah[0][b][u] = g_gammaH[(size_t)b*H_ + u] * h;   // t=0 slice
}

__global__ void __launch_bounds__(256) k_tr(const float* __restrict__ wgx,
                                            const float* __restrict__ wgh,
                                            const float* __restrict__ W1)
{
    int blk = blockIdx.x, k = threadIdx.x;
    if (blk < 256) g_wT[blk*D_ + k] = wgx[k*D_ + blk];
    else if (blk < 768) { int n = blk - 256; g_wT[D_*D_ + n*D_ + k] = wgh[k*H_ + n]; }
    else {
        int z = blk - 768;
        g_W1T[z*H_ + k]       = W1[k*10 + z];
        g_W1T[z*H_ + k + 256] = W1[(k+256)*10 + z];
    }
}

// per-group grid barrier (64 CTAs). 256 passes/launch -> replay-safe.
__device__ __forceinline__ void gridbar(int grp, unsigned &sense)
{
    __syncthreads();
    if (threadIdx.x == 0) {
        unsigned s = sense ^ 1, old;
        asm volatile("atom.acq_rel.gpu.global.add.u32 %0,[%1],1;"
                     : "=r"(old) : "l"(&g_barC[grp][0]));
        if (old == NCTA_GROUP-1) {
            asm volatile("st.relaxed.gpu.global.u32 [%0],%1;" :: "l"(&g_barC[grp][0]), "r"(0u));
            asm volatile("st.release.gpu.global.u32 [%0],%1;" :: "l"(&g_barS[grp][0]), "r"(s));
        } else {
            unsigned v;
            do {
                asm volatile("ld.acquire.gpu.global.u32 %0,[%1];" : "=r"(v) : "l"(&g_barS[grp][0]));
            } while (v != s);
        }
    }
    __syncthreads();
    sense ^= 1;
}

// ============================================================================
// Persistent recurrent loop (fp32 FFMA2 — exact; R10 structure).
// 256 CTAs in 4 independent (half,mb) groups of 64.  CTA = (half,mb,nb,kb):
//   tile b[b0,+64) x c[c0i,+128) x k[k0,+128), split-K 4.
// NEW vs R10: cell pre-computes ah(t+1) = gamma(t+1)⊙h into g_ah, so the
// per-step stage is a pure 32KB copy (half the L2 reads, no FMUL).
// ============================================================================
__device__ __forceinline__ void mm64(const float* __restrict__ As,
                                     const float* __restrict__ Bs,
                                     u64 acc[4][8], int tx, int ty)
{
    #pragma unroll 1
    for (int k4 = 0; k4 < 32; k4++) {
        float4 a4[4], w4[8];
        #pragma unroll
        for (int i = 0; i < 4; i++) a4[i] = *(const float4*)&As[(ty+16*i)*LDK + 4*k4];
        #pragma unroll
        for (int j = 0; j < 8; j++) w4[j] = *(const float4*)&Bs[(tx+16*j)*LDK + 4*k4];
        #pragma unroll
        for (int i = 0; i < 4; i++) {
            u64 alo = ((const u64*)&a4[i])[0], ahi = ((const u64*)&a4[i])[1];
            #pragma unroll
            for (int j = 0; j < 8; j++) {
                acc[i][j] = ffma2(alo, ((const u64*)&w4[j])[0], acc[i][j]);
                acc[i][j] = ffma2(ahi, ((const u64*)&w4[j])[1], acc[i][j]);
            }
        }
    }
}

__device__ __forceinline__ void load_tile(float* dst, const float* src,
                                          int rows, int row0, int ld, int col0)
{
    for (int i = threadIdx.x; i < rows*32; i += 256) {
        int r = i >> 5, q = (i & 31) << 2;
        *(float4*)&dst[r*LDK + q] = *(const float4*)&src[(size_t)(row0+r)*ld + col0 + q];
    }
}

__global__ void __launch_bounds__(256,2) k_loop(
    const float* __restrict__ Whh, const float* __restrict__ c0,
    const float* __restrict__ tp,  const float* __restrict__ wt,
    const float* __restrict__ ht,  const float* __restrict__ b1,
    const float* __restrict__ W2,  const float* __restrict__ b2,
    float* __restrict__ out)
{
    extern __shared__ float sm[];
    float *Wsm = sm;
    float *ahs = sm + 128*LDK;
    float *h1s = sm + 192*LDK;
    float *zs  = h1s + 512;
    float *tps = zs + 16;

    const int tid = threadIdx.x;
    const int half  = blockIdx.x >> 7;
    const int local = blockIdx.x & 127;
    const int grp   = blockIdx.x >> 6;           // (half, mb) group, 0..3
    const int kb = local & 3, nb = (local >> 2) & 15, mb = local >> 6;
    const int b0 = half*128 + mb*64, c0i = nb*128, k0 = kb*128;
    const int bc = half*128 + local;
    const int tx = tid & 15, ty = tid >> 4;
    unsigned sense = 0;

    load_tile(Wsm, Whh, 128, c0i, H_, k0);
    for (int i = tid; i < 128; i += 256) tps[i] = tp[bc*T_ + i];

    float c_reg[2], wtr[2], htr[2];
    #pragma unroll
    for (int q = 0; q < 2; q++) {
        c_reg[q] = c0[tid + 256*q];
        wtr[q]   = wt[tid + 256*q];
        htr[q]   = ht[tid + 256*q];
    }
    __syncthreads();

    for (int t = 0; t < T_; t++) {
        const int p = t & 1;

        // ---- stage: pure copy of ah tile + h1s for head(t-1) ----
        if (t > 0)
            for (int i = tid; i < 512; i += 256)
                h1s[i] = ldcg(&g_hbuf[p][bc][i]);
        for (int i = tid; i < 64*32; i += 256) {
            int r = i >> 5, q = (i & 31) << 2;
            float4 a = ldcg4(&g_ah[p][b0 + r][k0 + q]);
            *(float4*)&ahs[r*LDK + q] = a;
        }
        __syncthreads();

        // ---- output head for step t-1 (batch bc) ----
        if (t > 0) {
            int wid = tid >> 5, lane = tid & 31;
            for (int z = wid; z < 10; z += 8) {
                float s = 0.f;
                const float* wv = g_W1T + z*H_;
                #pragma unroll 4
                for (int k = lane; k < H_; k += 32) s = fmaf(h1s[k], __ldg(&wv[k]), s);
                #pragma unroll
                for (int off = 16; off; off >>= 1) s += __shfl_xor_sync(0xffffffffu, s, off);
                if (lane == 0) zs[z] = sigm(s + b1[z]);
            }
            __syncthreads();
            if (tid == 0) {
                float z0 = b2[0], z1 = b2[1];
                #pragma unroll
                for (int j = 0; j < 10; j++) {
                    z0 = fmaf(zs[j], W2[j*2 + 0], z0);
                    z1 = fmaf(zs[j], W2[j*2 + 1], z1);
                }
                z0 = sigm(z0); z1 = sigm(z1);
                float m = fmaxf(z0, z1);
                float e0 = expf(z0 - m), e1 = expf(z1 - m);
                float inv = 1.f/(e0 + e1);
                out[((size_t)(t-1)*B_ + bc)*2 + 0] = e0*inv;
                out[((size_t)(t-1)*B_ + bc)*2 + 1] = e1*inv;
            }
        }

        // ---- GEMM slice ----
        u64 acc[4][8] = {};
        mm64(ahs, Wsm, acc, tx, ty);
        #pragma unroll
        for (int i = 0; i < 4; i++) {
            int bg = b0 + ty + 16*i;
            #pragma unroll
            for (int j = 0; j < 8; j++) {
                F2U v; v.u = acc[i][j];
                stcg(&g_part[kb][bg][c0i + tx + 16*j], v.f.x + v.f.y);
            }
        }
        gridbar(grp, sense);

        // ---- cell (register c-state), batch bc; also writes ah(t+1) ----
        #pragma unroll
        for (int q = 0; q < 2; q++) {
            int u = tid + 256*q;
            const float* pre = &g_preGates[((size_t)t*B_ + bc)*G4H_];
            float gi = pre[u]        + ldcg(&g_part[0][bc][u])        + ldcg(&g_part[1][bc][u])
                                     + ldcg(&g_part[2][bc][u])        + ldcg(&g_part[3][bc][u]);
            float gf = pre[512 + u]  + ldcg(&g_part[0][bc][512 + u])  + ldcg(&g_part[1][bc][512 + u])
                                     + ldcg(&g_part[2][bc][512 + u])  + ldcg(&g_part[3][bc][512 + u]);
            float gg = pre[1024 + u] + ldcg(&g_part[0][bc][1024 + u]) + ldcg(&g_part[1][bc][1024 + u])
                                     + ldcg(&g_part[2][bc][1024 + u]) + ldcg(&g_part[3][bc][1024 + u]);
            float go = pre[1536 + u] + ldcg(&g_part[0][bc][1536 + u]) + ldcg(&g_part[1][bc][1536 + u])
                                     + ldcg(&g_part[2][bc][1536 + u]) + ldcg(&g_part[3][bc][1536 + u]);
            float gh = g_gammaH[((size_t)t*B_ + bc)*H_ + u];
            float c1 = sigm(gf)*(gh*c_reg[q]) + sigm(gi)*tanhf(gg);
            float h1 = sigm(go)*tanhf(c1);
            float gtv = sigm(tps[t]*wtr[q] + htr[q]);
            c_reg[q] = gtv*c1;
            float h1g = gtv*h1;
            stcg(&g_hbuf[p^1][bc][u], h1g);
            if (t < T_-1) {
                float gnext = g_gammaH[((size_t)(t+1)*B_ + bc)*H_ + u];
                stcg(&g_ah[p^1][bc][u], gnext * h1g);
            }
        }
        gridbar(grp, sense);
    }

    // ---- final head: step 127, h in hbuf[0], batch bc ----
    for (int i = tid; i < 512; i += 256)
        h1s[i] = ldcg(&g_hbuf[0][bc][i]);
    __syncthreads();
    {
        int wid = tid >> 5, lane = tid & 31;
        for (int z = wid; z < 10; z += 8) {
            float s = 0.f;
            const float* wv = g_W1T + z*H_;
            #pragma unroll 4
            for (int k = lane; k < H_; k += 32) s = fmaf(h1s[k], __ldg(&wv[k]), s);
            #pragma unroll
            for (int off = 16; off; off >>= 1) s += __shfl_xor_sync(0xffffffffu, s, off);
            if (lane == 0) zs[z] = sigm(s + b1[z]);
        }
        __syncthreads();
        if (tid == 0) {
            float z0 = b2[0], z1 = b2[1];
            #pragma unroll
            for (int j = 0; j < 10; j++) {
                z0 = fmaf(zs[j], W2[j*2 + 0], z0);
                z1 = fmaf(zs[j], W2[j*2 + 1], z1);
            }
            z0 = sigm(z0); z1 = sigm(z1);
            float m = fmaxf(z0, z1);
            float e0 = expf(z0 - m), e1 = expf(z1 - m);
            float inv = 1.f/(e0 + e1);
            out[((size_t)127*B_ + bc)*2 + 0] = e0*inv;
            out[((size_t)127*B_ + bc)*2 + 1] = e1*inv;
        }
    }
}

// ---------------------------------------------------------------------------
extern "C" void kernel_launch(void* const* d_in, const int* in_sizes, int n_in,
                              void* d_out, int out_size)
{
    const float* x     = (const float*)d_in[0];
    const float* dt    = (const float*)d_in[1];
    const float* mask  = (const float*)d_in[2];
    const float* tp    = (const float*)d_in[3];
    const float* xmean = (const float*)d_in[4];
    const float* h0    = (const float*)d_in[5];
    const float* c0    = (const float*)d_in[6];
    const float* wgx   = (const float*)d_in[7];
    const float* hgx   = (const float*)d_in[8];
    const float* wgh   = (const float*)d_in[9];
    const float* hgh   = (const float*)d_in[10];
    const float* wt    = (const float*)d_in[11];
    const float* ht    = (const float*)d_in[12];
    const float* Wih   = (const float*)d_in[13];
    const float* Whh   = (const float*)d_in[14];
    const float* bih   = (const float*)d_in[15];
    const float* bhh   = (const float*)d_in[16];
    const float* W1    = (const float*)d_in[17];
    const float* b1    = (const float*)d_in[18];
    const float* W2    = (const float*)d_in[19];
    const float* b2    = (const float*)d_in[20];
    float* out = (float*)d_out;

    const int LOOP_SMEM = (192*LDK + 512 + 16 + 128) * 4;
    static bool attr_done = false;
    if (!attr_done) {
        cudaFuncSetAttribute(k_g12_h, cudaFuncAttributeMaxDynamicSharedMemorySize, HM_SMEM);
        cudaFuncSetAttribute(k_g3_h,  cudaFuncAttributeMaxDynamicSharedMemorySize, HM_SMEM);
        cudaFuncSetAttribute(k_loop,  cudaFuncAttributeMaxDynamicSharedMemorySize, LOOP_SMEM);
        attr_done = true;
    }

    k_tr<<<778, 256>>>(wgx, wgh, W1);
    k_g12_h<<<dim3(BT_/128, 6),  256, HM_SMEM>>>(dt, hgx, hgh, x, mask, xmean, out);
    k_init<<<B_, H_>>>(h0);   // after k_g12_h: needs gammaH[0]
    k_g3_h<<<dim3(BT_/128, 16), 256, HM_SMEM>>>(out + XHAT_OFF, Wih, bih, bhh);
    k_loop<<<256, 256, LOOP_SMEM>>>(Whh, c0, tp, wt, ht, b1, W2, b2, out);
}

// round 17
// speedup vs baseline: 1.5193x; 1.5193x over previous
#include <cuda_runtime.h>
#include <cuda_bf16.h>
#include <math.h>
#include <stdint.h>

#define B_ 256
#define T_ 128
#define D_ 256
#define H_ 512
#define BT_ (B_*T_)
#define G4H_ 2048
#define XHAT_OFF (T_*B_*2)   /* outs [T,B,2] first, then xhats [T,B,D] */
#define LDK 132              /* SIMT loop smem row: Kc=128 + 4 pad */
#define NCTA_GROUP 64        /* loop: 4 independent groups of 64 CTAs */
#define LDF 72               /* bf16 frag-tile row stride: 144B, 16B-aligned, cf */

// ---- device scratch (allocation-free rule) ----
__device__ float g_gammaH[(size_t)T_*B_*H_];      // [T,B,H]
__device__ float g_preGates[(size_t)T_*B_*G4H_];  // [T,B,4H]
__device__ float g_part[4][B_][G4H_];             // split-K partials
__device__ float g_hbuf[2][B_][H_];               // double-buffered h
__device__ float g_wT[(D_+H_)*D_];                // wgxT [256,256] then wghT [512,256]
__device__ float g_W1T[10*H_];                    // W1 transposed [10][512]
__device__ unsigned g_barC[4][32];                // per-group barrier counter
__device__ unsigned g_barS[4][32];                // per-group barrier flag

typedef unsigned long long u64;
union F2U { u64 u; float2 f; };

__device__ __forceinline__ u64 ffma2(u64 a, u64 b, u64 c) {
    u64 d; asm("fma.rn.f32x2 %0,%1,%2,%3;" : "=l"(d) : "l"(a), "l"(b), "l"(c)); return d;
}
__device__ __forceinline__ float sigm(float x){ return 1.f/(1.f+expf(-x)); }
__device__ __forceinline__ float ldcg(const float* p){
    float v; asm volatile("ld.global.cg.f32 %0,[%1];" : "=f"(v) : "l"(p)); return v;
}
__device__ __forceinline__ float4 ldcg4(const float* p){
    float4 v; asm volatile("ld.global.cg.v4.f32 {%0,%1,%2,%3},[%4];"
        : "=f"(v.x),"=f"(v.y),"=f"(v.z),"=f"(v.w) : "l"(p)); return v;
}
__device__ __forceinline__ void stcg(float* p, float v){
    asm volatile("st.global.cg.f32 [%0],%1;" :: "l"(p), "f"(v));
}
__device__ __forceinline__ uint32_t s2u(const void* p){
    uint32_t a;
    asm("{ .reg .u64 t; cvta.to.shared.u64 t, %1; cvt.u32.u64 %0, t; }" : "=r"(a) : "l"(p));
    return a;
}

// ============================================================================
// HMMA bf16x3 GEMM machinery (mma.sync m16n8k16) — pre-GEMMs only.
// ============================================================================
__device__ __forceinline__ void ldm4(uint32_t* r, uint32_t addr){
    asm volatile("ldmatrix.sync.aligned.m8n8.x4.shared.b16 {%0,%1,%2,%3}, [%4];"
        : "=r"(r[0]),"=r"(r[1]),"=r"(r[2]),"=r"(r[3]) : "r"(addr));
}
__device__ __forceinline__ void mma_bf16(float* d, const uint32_t* a,
                                         uint32_t b0, uint32_t b1){
    asm volatile("mma.sync.aligned.m16n8k16.row.col.f32.bf16.bf16.f32 "
        "{%0,%1,%2,%3}, {%4,%5,%6,%7}, {%8,%9}, {%0,%1,%2,%3};"
        : "+f"(d[0]), "+f"(d[1]), "+f"(d[2]), "+f"(d[3])
        : "r"(a[0]), "r"(a[1]), "r"(a[2]), "r"(a[3]), "r"(b0), "r"(b1));
}
__device__ __forceinline__ void split4(float4 v, uint2& hi, uint2& lo){
    __nv_bfloat162 h01 = __floats2bfloat162_rn(v.x, v.y);
    __nv_bfloat162 h23 = __floats2bfloat162_rn(v.z, v.w);
    __nv_bfloat162 l01 = __floats2bfloat162_rn(v.x - __bfloat162float(h01.x),
                                               v.y - __bfloat162float(h01.y));
    __nv_bfloat162 l23 = __floats2bfloat162_rn(v.z - __bfloat162float(h23.x),
                                               v.w - __bfloat162float(h23.y));
    hi = make_uint2(*(uint32_t*)&h01, *(uint32_t*)&h23);
    lo = make_uint2(*(uint32_t*)&l01, *(uint32_t*)&l23);
}

// Pre-GEMM core: acc[2][8][4] += A[128 @arow0][256] @ B[128 @brow0][256]^T
__device__ __forceinline__ void hmma_gemm(
    __nv_bfloat16* sm, const float* __restrict__ A, int arow0, int lda,
    const float* __restrict__ Bsrc, int brow0, int ldb, float acc[2][8][4])
{
    __nv_bfloat16 *sAhi = sm, *sAlo = sm + 128*LDF;
    __nv_bfloat16 *sBhi = sm + 2*128*LDF, *sBlo = sm + 3*128*LDF;
    const int tid = threadIdx.x, lane = tid & 31, wid = tid >> 5;
    const int wm = wid & 3, wn = wid >> 2;
    const int g = lane >> 3, r8 = lane & 7;

    for (int ch = 0; ch < 4; ch++) {
        const int k0 = ch*64;
        if (ch) __syncthreads();
        #pragma unroll 4
        for (int i = tid; i < 2048; i += 256) {
            int rr = i >> 4, q = (i & 15) << 2;
            uint2 hi, lo;
            split4(*(const float4*)&A[(size_t)(arow0+rr)*lda + k0 + q], hi, lo);
            *(uint2*)&sAhi[rr*LDF + q] = hi;
            *(uint2*)&sAlo[rr*LDF + q] = lo;
        }
        #pragma unroll 4
        for (int i = tid; i < 2048; i += 256) {
            int rr = i >> 4, q = (i & 15) << 2;
            uint2 hi, lo;
            split4(*(const float4*)&Bsrc[(size_t)(brow0+rr)*ldb + k0 + q], hi, lo);
            *(uint2*)&sBhi[rr*LDF + q] = hi;
            *(uint2*)&sBlo[rr*LDF + q] = lo;
        }
        __syncthreads();
        #pragma unroll
        for (int ks = 0; ks < 4; ks++) {
            const int kk = ks*16;
            uint32_t ahi[2][4], alo[2][4], bhi[4][4], blo[4][4];
            #pragma unroll
            for (int mi = 0; mi < 2; mi++) {
                int m = wm*32 + mi*16 + (g & 1)*8 + r8;
                int k = kk + (g >> 1)*8;
                ldm4(ahi[mi], s2u(&sAhi[m*LDF + k]));
                ldm4(alo[mi], s2u(&sAlo[m*LDF + k]));
            }
            #pragma unroll
            for (int np = 0; np < 4; np++) {
                int n = wn*64 + np*16 + (g >> 1)*8 + r8;
                int k = kk + (g & 1)*8;
                ldm4(bhi[np], s2u(&sBhi[n*LDF + k]));
                ldm4(blo[np], s2u(&sBlo[n*LDF + k]));
            }
            #pragma unroll
            for (int mi = 0; mi < 2; mi++)
                #pragma unroll
                for (int nj = 0; nj < 8; nj++) {
                    uint32_t h0 = bhi[nj>>1][(nj&1)*2], h1 = bhi[nj>>1][(nj&1)*2+1];
                    uint32_t l0 = blo[nj>>1][(nj&1)*2], l1 = blo[nj>>1][(nj&1)*2+1];
                    mma_bf16(acc[mi][nj], ahi[mi], h0, h1);
                    mma_bf16(acc[mi][nj], ahi[mi], l0, l1);
                    mma_bf16(acc[mi][nj], alo[mi], h0, h1);
                }
        }
    }
}
#define HM_SMEM (4*128*LDF*2)

// ---------------------------------------------------------------------------
// G12 (HMMA): gamma_x (+imputation->xhat) and gamma_h.  grid (BT/128, 6).
// ---------------------------------------------------------------------------
__global__ void __launch_bounds__(256,2) k_g12_h(
    const float* __restrict__ dt,  const float* __restrict__ hgx,
    const float* __restrict__ hgh, const float* __restrict__ x,
    const float* __restrict__ mask, const float* __restrict__ xmean,
    float* __restrict__ out)
{
    extern __shared__ __nv_bfloat16 smb[];
    float acc[2][8][4] = {};
    const int m0 = blockIdx.x*128, n0 = blockIdx.y*128;
    hmma_gemm(smb, dt, m0, D_, (const float*)g_wT, n0, D_, acc);

    const int lane = threadIdx.x & 31, wid = threadIdx.x >> 5;
    const int wm = wid & 3, wn = wid >> 2;
    const int tg = lane >> 2, tc = (lane & 3)*2;

    #pragma unroll
    for (int mi = 0; mi < 2; mi++) {
        #pragma unroll
        for (int nj = 0; nj < 8; nj++) {
            const float* a4 = acc[mi][nj];
            int ng = n0 + wn*64 + nj*8 + tc;
            #pragma unroll
            for (int h = 0; h < 2; h++) {
                int row = m0 + wm*32 + mi*16 + tg + h*8;   // = b*T + t
                int b = row >> 7, t = row & (T_-1);
                float v0 = a4[h*2], v1 = a4[h*2+1];
                if (blockIdx.y < 2) {
                    int d = ng;
                    float o[2];
                    #pragma unroll
                    for (int e = 0; e < 2; e++) {
                        float v = e ? v1 : v0; int dd = d + e;
                        float gm = expf(-fmaxf(v + hgx[dd], 0.f));
                        float mv = mask[(size_t)row*D_ + dd];
                        float xt = x[(size_t)row*D_ + dd];
                        float xm = xmean[dd];
                        float imp = (t == 0) ? xm
                                  : fmaf(gm, x[(size_t)(row-1)*D_ + dd], (1.f-gm)*xm);
                        o[e] = xt*mv + (1.f-mv)*imp;
                    }
                    *(float2*)&out[XHAT_OFF + ((size_t)t*B_ + b)*D_ + d] = make_float2(o[0], o[1]);
                } else {
                    int u = ng - 256;
                    float2 o;
                    o.x = expf(-fmaxf(v0 + hgh[u],   0.f));
                    o.y = expf(-fmaxf(v1 + hgh[u+1], 0.f));
                    *(float2*)&g_gammaH[((size_t)t*B_ + b)*H_ + u] = o;
                }
            }
        }
    }
}

// ---------------------------------------------------------------------------
// G3 (HMMA): pre_gates = xs @ W_ih^T + b_ih + b_hh.  grid (BT/128, 16).
// ---------------------------------------------------------------------------
__global__ void __launch_bounds__(256,2) k_g3_h(
    const float* __restrict__ xsrc, const float* __restrict__ Wih,
    const float* __restrict__ bih,  const float* __restrict__ bhh)
{
    extern __shared__ __nv_bfloat16 smb[];
    float acc[2][8][4] = {};
    const int m0 = blockIdx.x*128, n0 = blockIdx.y*128;
    hmma_gemm(smb, xsrc, m0, D_, Wih, n0, D_, acc);

    const int lane = threadIdx.x & 31, wid = threadIdx.x >> 5;
    const int wm = wid & 3, wn = wid >> 2;
    const int tg = lane >> 2, tc = (lane & 3)*2;

    #pragma unroll
    for (int mi = 0; mi < 2; mi++) {
        #pragma unroll
        for (int nj = 0; nj < 8; nj++) {
            const float* a4 = acc[mi][nj];
            int n = n0 + wn*64 + nj*8 + tc;
            float bi0 = bih[n] + bhh[n], bi1 = bih[n+1] + bhh[n+1];
            #pragma unroll
            for (int h = 0; h < 2; h++) {
                int row = m0 + wm*32 + mi*16 + tg + h*8;   // = t*B + b
                *(float2*)&g_preGates[(size_t)row*G4H_ + n] =
                    make_float2(a4[h*2] + bi0, a4[h*2+1] + bi1);
            }
        }
    }
}

// ============================================================================
// SIMT persistent recurrent loop (fp32 FFMA2 — exact)
// ============================================================================
__device__ __forceinline__ void mm64(const float* __restrict__ As,
                                     const float* __restrict__ Bs,
                                     u64 acc[4][8], int tx, int ty)
{
    #pragma unroll 1
    for (int k4 = 0; k4 < 32; k4++) {
        float4 a4[4], w4[8];
        #pragma unroll
        for (int i = 0; i < 4; i++) a4[i] = *(const float4*)&As[(ty+16*i)*LDK + 4*k4];
        #pragma unroll
        for (int j = 0; j < 8; j++) w4[j] = *(const float4*)&Bs[(tx+16*j)*LDK + 4*k4];
        #pragma unroll
        for (int i = 0; i < 4; i++) {
            u64 alo = ((const u64*)&a4[i])[0], ahi = ((const u64*)&a4[i])[1];
            #pragma unroll
            for (int j = 0; j < 8; j++) {
                acc[i][j] = ffma2(alo, ((const u64*)&w4[j])[0], acc[i][j]);
                acc[i][j] = ffma2(ahi, ((const u64*)&w4[j])[1], acc[i][j]);
            }
        }
    }
}

__device__ __forceinline__ void load_tile(float* dst, const float* src,
                                          int rows, int row0, int ld, int col0)
{
    for (int i = threadIdx.x; i < rows*32; i += 256) {
        int r = i >> 5, q = (i & 31) << 2;
        *(float4*)&dst[r*LDK + q] = *(const float4*)&src[(size_t)(row0+r)*ld + col0 + q];
    }
}

__global__ void __launch_bounds__(H_) k_init(const float* __restrict__ h0)
{
    g_hbuf[0][blockIdx.x][threadIdx.x] = h0[threadIdx.x];
}

__global__ void __launch_bounds__(256) k_tr(const float* __restrict__ wgx,
                                            const float* __restrict__ wgh,
                                            const float* __restrict__ W1)
{
    int blk = blockIdx.x, k = threadIdx.x;
    if (blk < 256) g_wT[blk*D_ + k] = wgx[k*D_ + blk];
    else if (blk < 768) { int n = blk - 256; g_wT[D_*D_ + n*D_ + k] = wgh[k*H_ + n]; }
    else {
        int z = blk - 768;
        g_W1T[z*H_ + k]       = W1[k*10 + z];
        g_W1T[z*H_ + k + 256] = W1[(k+256)*10 + z];
    }
}

// per-group grid barrier (64 CTAs). 256 passes/launch -> replay-safe.
__device__ __forceinline__ void gridbar(int grp, unsigned &sense)
{
    __syncthreads();
    if (threadIdx.x == 0) {
        unsigned s = sense ^ 1, old;
        asm volatile("atom.acq_rel.gpu.global.add.u32 %0,[%1],1;"
                     : "=r"(old) : "l"(&g_barC[grp][0]));
        if (old == NCTA_GROUP-1) {
            asm volatile("st.relaxed.gpu.global.u32 [%0],%1;" :: "l"(&g_barC[grp][0]), "r"(0u));
            asm volatile("st.release.gpu.global.u32 [%0],%1;" :: "l"(&g_barS[grp][0]), "r"(s));
        } else {
            unsigned v;
            do {
                asm volatile("ld.acquire.gpu.global.u32 %0,[%1];" : "=r"(v) : "l"(&g_barS[grp][0]));
            } while (v != s);
        }
    }
    __syncthreads();
    sense ^= 1;
}

// ---------------------------------------------------------------------------
// Persistent loop: 256 CTAs in 4 independent (half,mb) groups of 64.
// CTA = (half,mb,nb,kb): tile b[b0,+64) x c[c0i,+128) x k[k0,+128).
// ---------------------------------------------------------------------------
__global__ void __launch_bounds__(256,2) k_loop(
    const float* __restrict__ Whh, const float* __restrict__ c0,
    const float* __restrict__ tp,  const float* __restrict__ wt,
    const float* __restrict__ ht,  const float* __restrict__ b1,
    const float* __restrict__ W2,  const float* __restrict__ b2,
    float* __restrict__ out)
{
    extern __shared__ float sm[];
    float *Wsm = sm;
    float *ahs = sm + 128*LDK;
    float *h1s = sm + 192*LDK;
    float *zs  = h1s + 512;
    float *tps = zs + 16;

    const int tid = threadIdx.x;
    const int half  = blockIdx.x >> 7;
    const int local = blockIdx.x & 127;
    const int grp   = blockIdx.x >> 6;           // (half, mb) group, 0..3
    const int kb = local & 3, nb = (local >> 2) & 15, mb = local >> 6;
    const int b0 = half*128 + mb*64, c0i = nb*128, k0 = kb*128;
    const int bc = half*128 + local;
    const int tx = tid & 15, ty = tid >> 4;
    unsigned sense = 0;

    load_tile(Wsm, Whh, 128, c0i, H_, k0);
    for (int i = tid; i < 128; i += 256) tps[i] = tp[bc*T_ + i];

    float c_reg[2], wtr[2], htr[2];
    #pragma unroll
    for (int q = 0; q < 2; q++) {
        c_reg[q] = c0[tid + 256*q];
        wtr[q]   = wt[tid + 256*q];
        htr[q]   = ht[tid + 256*q];
    }
    __syncthreads();

    for (int t = 0; t < T_; t++) {
        const int p = t & 1;

        if (t > 0)
            for (int i = tid; i < 512; i += 256)
                h1s[i] = ldcg(&g_hbuf[p][bc][i]);
        for (int i = tid; i < 64*32; i += 256) {
            int r = i >> 5, q = (i & 31) << 2;
            int bg = b0 + r;
            float4 g = *(const float4*)&g_gammaH[((size_t)t*B_ + bg)*H_ + k0 + q];
            float4 h = ldcg4(&g_hbuf[p][bg][k0 + q]);
            g.x *= h.x; g.y *= h.y; g.z *= h.z; g.w *= h.w;
            *(float4*)&ahs[r*LDK + q] = g;
        }
        __syncthreads();

        if (t > 0) {
            int wid = tid >> 5, lane = tid & 31;
            for (int z = wid; z < 10; z += 8) {
                float s = 0.f;
                const float* wv = g_W1T + z*H_;
                #pragma unroll 4
                for (int k = lane; k < H_; k += 32) s = fmaf(h1s[k], __ldg(&wv[k]), s);
                #pragma unroll
                for (int off = 16; off; off >>= 1) s += __shfl_xor_sync(0xffffffffu, s, off);
                if (lane == 0) zs[z] = sigm(s + b1[z]);
            }
            __syncthreads();
            if (tid == 0) {
                float z0 = b2[0], z1 = b2[1];
                #pragma unroll
                for (int j = 0; j < 10; j++) {
                    z0 = fmaf(zs[j], W2[j*2 + 0], z0);
                    z1 = fmaf(zs[j], W2[j*2 + 1], z1);
                }
                z0 = sigm(z0); z1 = sigm(z1);
                float m = fmaxf(z0, z1);
                float e0 = expf(z0 - m), e1 = expf(z1 - m);
                float inv = 1.f/(e0 + e1);
                out[((size_t)(t-1)*B_ + bc)*2 + 0] = e0*inv;
                out[((size_t)(t-1)*B_ + bc)*2 + 1] = e1*inv;
            }
        }

        u64 acc[4][8] = {};
        mm64(ahs, Wsm, acc, tx, ty);
        #pragma unroll
        for (int i = 0; i < 4; i++) {
            int bg = b0 + ty + 16*i;
            #pragma unroll
            for (int j = 0; j < 8; j++) {
                F2U v; v.u = acc[i][j];
                stcg(&g_part[kb][bg][c0i + tx + 16*j], v.f.x + v.f.y);
            }
        }
        gridbar(grp, sense);

        #pragma unroll
        for (int q = 0; q < 2; q++) {
            int u = tid + 256*q;
            const float* pre = &g_preGates[((size_t)t*B_ + bc)*G4H_];
            float gi = pre[u]        + ldcg(&g_part[0][bc][u])        + ldcg(&g_part[1][bc][u])
                                     + ldcg(&g_part[2][bc][u])        + ldcg(&g_part[3][bc][u]);
            float gf = pre[512 + u]  + ldcg(&g_part[0][bc][512 + u])  + ldcg(&g_part[1][bc][512 + u])
                                     + ldcg(&g_part[2][bc][512 + u])  + ldcg(&g_part[3][bc][512 + u]);
            float gg = pre[1024 + u] + ldcg(&g_part[0][bc][1024 + u]) + ldcg(&g_part[1][bc][1024 + u])
                                     + ldcg(&g_part[2][bc][1024 + u]) + ldcg(&g_part[3][bc][1024 + u]);
            float go = pre[1536 + u] + ldcg(&g_part[0][bc][1536 + u]) + ldcg(&g_part[1][bc][1536 + u])
                                     + ldcg(&g_part[2][bc][1536 + u]) + ldcg(&g_part[3][bc][1536 + u]);
            float gh = g_gammaH[((size_t)t*B_ + bc)*H_ + u];
            float c1 = sigm(gf)*(gh*c_reg[q]) + sigm(gi)*tanhf(gg);
            float h1 = sigm(go)*tanhf(c1);
            float gtv = sigm(tps[t]*wtr[q] + htr[q]);
            c_reg[q] = gtv*c1;
            stcg(&g_hbuf[p^1][bc][u], gtv*h1);
        }
        gridbar(grp, sense);
    }

    for (int i = tid; i < 512; i += 256)
        h1s[i] = ldcg(&g_hbuf[0][bc][i]);
    __syncthreads();
    {
        int wid = tid >> 5, lane = tid & 31;
        for (int z = wid; z < 10; z += 8) {
            float s = 0.f;
            const float* wv = g_W1T + z*H_;
            #pragma unroll 4
            for (int k = lane; k < H_; k += 32) s = fmaf(h1s[k], __ldg(&wv[k]), s);
            #pragma unroll
            for (int off = 16; off; off >>= 1) s += __shfl_xor_sync(0xffffffffu, s, off);
            if (lane == 0) zs[z] = sigm(s + b1[z]);
        }
        __syncthreads();
        if (tid == 0) {
            float z0 = b2[0], z1 = b2[1];
            #pragma unroll
            for (int j = 0; j < 10; j++) {
                z0 = fmaf(zs[j], W2[j*2 + 0], z0);
                z1 = fmaf(zs[j], W2[j*2 + 1], z1);
            }
            z0 = sigm(z0); z1 = sigm(z1);
            float m = fmaxf(z0, z1);
            float e0 = expf(z0 - m), e1 = expf(z1 - m);
            float inv = 1.f/(e0 + e1);
            out[((size_t)127*B_ + bc)*2 + 0] = e0*inv;
            out[((size_t)127*B_ + bc)*2 + 1] = e1*inv;
        }
    }
}

// ---------------------------------------------------------------------------
extern "C" void kernel_launch(void* const* d_in, const int* in_sizes, int n_in,
                              void* d_out, int out_size)
{
    const float* x     = (const float*)d_in[0];
    const float* dt    = (const float*)d_in[1];
    const float* mask  = (const float*)d_in[2];
    const float* tp    = (const float*)d_in[3];
    const float* xmean = (const float*)d_in[4];
    const float* h0    = (const float*)d_in[5];
    const float* c0    = (const float*)d_in[6];
    const float* wgx   = (const float*)d_in[7];
    const float* hgx   = (const float*)d_in[8];
    const float* wgh   = (const float*)d_in[9];
    const float* hgh   = (const float*)d_in[10];
    const float* wt    = (const float*)d_in[11];
    const float* ht    = (const float*)d_in[12];
    const float* Wih   = (const float*)d_in[13];
    const float* Whh   = (const float*)d_in[14];
    const float* bih   = (const float*)d_in[15];
    const float* bhh   = (const float*)d_in[16];
    const float* W1    = (const float*)d_in[17];
    const float* b1    = (const float*)d_in[18];
    const float* W2    = (const float*)d_in[19];
    const float* b2    = (const float*)d_in[20];
    float* out = (float*)d_out;

    const int LOOP_SMEM = (192*LDK + 512 + 16 + 128) * 4;
    static bool attr_done = false;
    if (!attr_done) {
        cudaFuncSetAttribute(k_g12_h, cudaFuncAttributeMaxDynamicSharedMemorySize, HM_SMEM);
        cudaFuncSetAttribute(k_g3_h,  cudaFuncAttributeMaxDynamicSharedMemorySize, HM_SMEM);
        cudaFuncSetAttribute(k_loop,  cudaFuncAttributeMaxDynamicSharedMemorySize, LOOP_SMEM);
        attr_done = true;
    }

    k_init<<<B_, H_>>>(h0);
    k_tr<<<778, 256>>>(wgx, wgh, W1);
    k_g12_h<<<dim3(BT_/128, 6),  256, HM_SMEM>>>(dt, hgx, hgh, x, mask, xmean, out);
    k_g3_h<<<dim3(BT_/128, 16), 256, HM_SMEM>>>(out + XHAT_OFF, Wih, bih, bhh);
    k_loop<<<256, 256, LOOP_SMEM>>>(Whh, c0, tp, wt, ht, b1, W2, b2, out);
}